// round 13
// baseline (speedup 1.0000x reference)
#include <cuda_runtime.h>
#include <cuda_bf16.h>
#include <cuda_fp16.h>
#include <cstdint>
#include <cstddef>

// Problem constants
#define DI  512      // D_IN
#define DM  1024     // D_MEM
#define BB  8        // batch
#define SS  2048     // seq len
#define RR  (BB*SS)  // 16384 rows
#define NCH2 16      // chunks per batch (chunk = 128 steps)

// -------- scratch (static device globals; no allocation) --------
__device__ float g_Wpart[4*DI*DI];                 // split-K partials of W
__device__ float g_c[DI];                          // c = Wo @ bi
__device__ float g_y0[BB*DI];                      // memory @ Wo^T
__device__ float g_lf[BB*NCH2*DI];                 // per-chunk zero-init scan finals
__device__ float g_carry[BB*NCH2*DI];
__device__ float g_xwp[3*4*BB*DI];                 // last-3-chunk 4-way weighted x partials
__device__ float g_xw[BB*DI];
__device__ __align__(16) __half g_wh[DI*DI];       // W in fp16 (single matrix)

// =========================== PTX helpers ===========================
__device__ __forceinline__ uint32_t smem_u32_of(const void* p) {
    uint32_t a;
    asm("{ .reg .u64 t; cvta.to.shared.u64 t, %1; cvt.u32.u64 %0, t; }" : "=r"(a) : "l"(p));
    return a;
}
__device__ __forceinline__ void cp_async16(uint32_t dst, const void* src) {
    asm volatile("cp.async.cg.shared.global [%0], [%1], 16;" :: "r"(dst), "l"(src) : "memory");
}
__device__ __forceinline__ void cp_commit() {
    asm volatile("cp.async.commit_group;" ::: "memory");
}
template<int N> __device__ __forceinline__ void cp_wait() {
    asm volatile("cp.async.wait_group %0;" :: "n"(N) : "memory");
}
__device__ __forceinline__ void ldsm4(uint32_t* r, uint32_t addr) {
    asm volatile("ldmatrix.sync.aligned.m8n8.x4.shared.b16 {%0,%1,%2,%3}, [%4];"
                 : "=r"(r[0]), "=r"(r[1]), "=r"(r[2]), "=r"(r[3]) : "r"(addr));
}
__device__ __forceinline__ void mma16816(float* c, const uint32_t* a, const uint32_t* b) {
    asm volatile(
        "mma.sync.aligned.m16n8k16.row.col.f32.f16.f16.f32 "
        "{%0,%1,%2,%3}, {%4,%5,%6,%7}, {%8,%9}, {%0,%1,%2,%3};"
        : "+f"(c[0]), "+f"(c[1]), "+f"(c[2]), "+f"(c[3])
        : "r"(a[0]), "r"(a[1]), "r"(a[2]), "r"(a[3]), "r"(b[0]), "r"(b[1]));
}

// fp32 x8 -> fp16 hi/lo x8
__device__ __forceinline__ void cvt8h(const float4 a, const float4 b, uint4& H, uint4& L) {
    float f[8] = {a.x, a.y, a.z, a.w, b.x, b.y, b.z, b.w};
    uint32_t h[4], l[4];
    #pragma unroll
    for (int q = 0; q < 4; q++) {
        __half2 hh = __floats2half2_rn(f[2*q], f[2*q+1]);
        float r0 = f[2*q]   - __half2float(__low2half(hh));
        float r1 = f[2*q+1] - __half2float(__high2half(hh));
        __half2 ll = __floats2half2_rn(r0, r1);
        h[q] = *(uint32_t*)&hh;
        l[q] = *(uint32_t*)&ll;
    }
    H = make_uint4(h[0], h[1], h[2], h[3]);
    L = make_uint4(l[0], l[1], l[2], l[3]);
}

// ================== fused tensor-core GEMM + zero-init scan (FROZEN R12 body) ==================
#define KCH    32
#define NCHK   (DI/KCH)          // 16
#define ROWB   80                // padded smem row stride (64B data + 16B pad)
#define MATB   (128*ROWB)        // 10240 bytes per matrix tile
#define STG_B  (3*MATB)          // 30720 per stage (AH, AL, BH)
#define OFF_F  67584             // after epilogue S region (128*132*4)
#define OFF_BO 68608             // bo strip: 128 floats
#define OFF_CS 69120             // c strip: 128 floats
#define GEMM_SMEM 69632

__global__ void __launch_bounds__(256, 2)
mma_gemm_kernel(const float* __restrict__ x,
                const __half* __restrict__ wh,
                const float* __restrict__ cbias, const float* __restrict__ bo,
                float* __restrict__ out, float* __restrict__ lf)
{
    extern __shared__ char smem[];
    const uint32_t sbase = smem_u32_of(smem);
    const int tid  = threadIdx.x;
    const int wid  = tid >> 5;
    const int lane = tid & 31;
    const int wm   = wid & 3;
    const int wn   = wid >> 2;
    const int m0   = blockIdx.y * 128;
    const int n0g  = blockIdx.x * 128;
    const int bch  = blockIdx.y;   // b = bch>>4, chunk = bch&15

    float* F_sm  = (float*)(smem + OFF_F);
    float* bo_sm = (float*)(smem + OFF_BO);
    float* cs_sm = (float*)(smem + OFF_CS);
    if (tid < 128) {
        bo_sm[tid] = bo[n0g + tid];
        cs_sm[tid] = cbias[n0g + tid];
    }

    const float* xg = x + (size_t)m0 * DI;
    const __half* bhg = wh + (size_t)n0g * DI;

    const int lr  = lane & 7;
    const int blk = lane >> 3;
    const uint32_t a_off = (uint32_t)((((blk & 1) * 8 + lr) * ROWB) + ((blk >> 1) * 16));
    const uint32_t b_off = (uint32_t)((((blk >> 1) * 8 + lr) * ROWB) + ((blk & 1) * 16));

    float acc[2][8][4];
    #pragma unroll
    for (int i = 0; i < 2; i++)
        #pragma unroll
        for (int j = 0; j < 8; j++)
            #pragma unroll
            for (int q = 0; q < 4; q++) acc[i][j][q] = 0.f;

    float4 xr[4];

    auto ldA = [&](int ch) {
        const int k0 = ch * KCH;
        #pragma unroll
        for (int u = 0; u < 2; u++) {
            const int idx2 = tid * 2 + u;
            const int r = idx2 >> 2, j = idx2 & 3;
            const float4* sp = (const float4*)(xg + (size_t)r * DI + k0 + j * 8);
            xr[u*2+0] = sp[0];
            xr[u*2+1] = sp[1];
        }
    };
    auto stA = [&](int ch) {
        const uint32_t stg = (uint32_t)((ch & 1) * STG_B);
        #pragma unroll
        for (int u = 0; u < 2; u++) {
            const int idx2 = tid * 2 + u;
            const int r = idx2 >> 2, j = idx2 & 3;
            uint4 H, L;
            cvt8h(xr[u*2+0], xr[u*2+1], H, L);
            *(uint4*)(smem + stg + r * ROWB + j * 16)        = H;
            *(uint4*)(smem + stg + MATB + r * ROWB + j * 16) = L;
        }
    };
    auto issueB = [&](int ch) {
        const int k0 = ch * KCH;
        const uint32_t stg = sbase + (uint32_t)((ch & 1) * STG_B) + 2 * MATB;
        #pragma unroll
        for (int t = 0; t < 2; t++) {
            const int i   = (t << 8) + tid;     // 0..511
            const int row = i >> 2, j = i & 3;
            const uint32_t dst = stg + (uint32_t)(row * ROWB + j * 16);
            cp_async16(dst, bhg + (size_t)row * DI + k0 + j * 8);
        }
        cp_commit();
    };

    ldA(0);
    issueB(0);

    for (int ch = 0; ch < NCHK; ch++) {
        if (ch + 1 < NCHK) issueB(ch + 1);
        stA(ch);
        if (ch + 1 < NCHK) ldA(ch + 1);
        if (ch + 1 < NCHK) cp_wait<1>(); else cp_wait<0>();
        __syncthreads();

        const uint32_t stg = sbase + (uint32_t)((ch & 1) * STG_B);
        const uint32_t sAH = stg;
        const uint32_t sAL = stg + MATB;
        const uint32_t sBH = stg + 2 * MATB;

        #pragma unroll
        for (int kk = 0; kk < 2; kk++) {
            const uint32_t kb = (uint32_t)(kk * 32);
            uint32_t ah[2][4], al[2][4];
            #pragma unroll
            for (int mt = 0; mt < 2; mt++) {
                const uint32_t ro = (uint32_t)((wm * 32 + mt * 16) * ROWB) + kb + a_off;
                ldsm4(ah[mt], sAH + ro);
                ldsm4(al[mt], sAL + ro);
            }
            #pragma unroll
            for (int nb = 0; nb < 4; nb++) {
                const uint32_t ro = (uint32_t)((wn * 64 + nb * 16) * ROWB) + kb + b_off;
                uint32_t bh[4];
                ldsm4(bh, sBH + ro);
                #pragma unroll
                for (int mt = 0; mt < 2; mt++) {
                    mma16816(acc[mt][2*nb+0], ah[mt], bh + 0);
                    mma16816(acc[mt][2*nb+1], ah[mt], bh + 2);
                    mma16816(acc[mt][2*nb+0], al[mt], bh + 0);
                    mma16816(acc[mt][2*nb+1], al[mt], bh + 2);
                }
            }
        }
        __syncthreads();
    }

    // ---- epilogue: dump acc to smem, zero-init local scan, +bo, write out; emit lf ----
    float* S = (float*)smem;   // [128][132] fp32
    #pragma unroll
    for (int mt = 0; mt < 2; mt++) {
        const int r0 = wm * 32 + mt * 16 + (lane >> 2);
        #pragma unroll
        for (int nt = 0; nt < 8; nt++) {
            const int c0 = wn * 64 + nt * 8 + ((lane & 3) * 2);
            S[r0 * 132 + c0]       = acc[mt][nt][0];
            S[r0 * 132 + c0 + 1]   = acc[mt][nt][1];
            S[(r0+8) * 132 + c0]     = acc[mt][nt][2];
            S[(r0+8) * 132 + c0 + 1] = acc[mt][nt][3];
        }
    }
    __syncthreads();

    const int col  = tid & 127;
    const int half = tid >> 7;
    const float cv = cs_sm[col];
    {
        const int tb = half * 64;
        float o = 0.f;
        #pragma unroll 4
        for (int t = 0; t < 64; t++) {
            o = o * 0.9f + 0.1f * (S[(tb + t) * 132 + col] + cv);
            S[(tb + t) * 132 + col] = o;
        }
        F_sm[half * 128 + col] = o;
    }
    __syncthreads();

    if (half == 1) {
        const float f0 = F_sm[col];   // half-0 final
        float p = 0.9f, last = 0.f;
        #pragma unroll 4
        for (int t = 0; t < 64; t++) {
            last = S[(64 + t) * 132 + col] + p * f0;
            S[(64 + t) * 132 + col] = last;
            p *= 0.9f;
        }
        lf[(size_t)bch * DI + n0g + col] = last;   // chunk-final (zero-init)
    }
    __syncthreads();

    #pragma unroll
    for (int it = 0; it < 16; it++) {
        const int idx = tid + it * 256;
        const int row = idx >> 5;
        const int q   = idx & 31;
        float4 s = *(float4*)&S[row * 132 + q * 4];
        const int lc = q * 4;
        s.x += bo_sm[lc]; s.y += bo_sm[lc+1]; s.z += bo_sm[lc+2]; s.w += bo_sm[lc+3];
        *(float4*)(out + (size_t)(m0 + row) * DI + n0g + lc) = s;
    }
}

#define XC1 0.03433683820292512f            // 0.9^32
#define XC2 (XC1*XC1)
#define XC3 (XC2*XC1)
#define P128 1.3900845237714473e-06f        // 0.9^128

// ===== carry sweep + xw combine (merged; grid 16 x 512) =====
__global__ void carry_kernel(const float* __restrict__ lf, const float* __restrict__ y0,
                             float* __restrict__ carry,
                             const float* __restrict__ part, float* __restrict__ xw)
{
    const int i = threadIdx.x;
    if (blockIdx.x < 8) {
        const int b = blockIdx.x;
        float lfv[NCH2];
        #pragma unroll
        for (int ch = 0; ch < NCH2; ch++)
            lfv[ch] = lf[(size_t)(b * NCH2 + ch) * DI + i];
        float c = y0[b * DI + i];
        #pragma unroll
        for (int ch = 0; ch < NCH2; ch++) {
            carry[(size_t)(b * NCH2 + ch) * DI + i] = c;
            c = c * P128 + lfv[ch];
        }
    } else {
        const int b = blockIdx.x - 8;
        float v[12];
        #pragma unroll
        for (int q = 0; q < 12; q++)
            v[q] = part[((size_t)q * BB + b) * DI + i];
        float xwc[3];
        #pragma unroll
        for (int cc = 0; cc < 3; cc++)
            xwc[cc] = v[cc*4+3] + XC1*v[cc*4+2] + XC2*v[cc*4+1] + XC3*v[cc*4+0];
        xw[b * DI + i] = xwc[2] + P128 * xwc[1] + (P128 * P128) * xwc[0];
    }
}

// ===== fixup (out += 0.9^{t+1}*carry) + fm (final memory) merged; grid 640 x 512 =====
__global__ void fixfm_kernel(const float* __restrict__ carry, float* __restrict__ out,
                             const float* __restrict__ xw, const float* __restrict__ Wi,
                             const float* __restrict__ bi, float* __restrict__ fm)
{
    const int blk = blockIdx.x;
    const int tid = threadIdx.x;
    if (blk < 128) {
        const int ch = blk & 15, b = blk >> 4, i = tid;
        const float cr = carry[(size_t)(b * NCH2 + ch) * DI + i];
        if (cr == 0.f) return;
        float p = 0.9f;
        float* op = out + (size_t)(b * SS + ch * 128) * DI + i;
        #pragma unroll 4
        for (int t = 0; t < 128; t++) {
            op[(size_t)t * DI] += p * cr;
            p *= 0.9f;
        }
    } else {
        const int w = ((blk - 128) * 512 + tid) >> 5;   // 0..8191
        const int lane = tid & 31;
        const int b = w / DM, m = w % DM;
        float s = 0.f;
        for (int j = lane; j < DI; j += 32) s += xw[b * DI + j] * Wi[(size_t)m * DI + j];
        #pragma unroll
        for (int o = 16; o; o >>= 1) s += __shfl_down_sync(0xffffffffu, s, o);
        if (!lane) fm[w] = s + bi[m];
    }
}

// ================== W = Wo @ Wi, split-K=4 partials (Wi read directly) ==========
__global__ void __launch_bounds__(256)
wgemm_kernel(const float* __restrict__ Wo, const float* __restrict__ Wi,
             float* __restrict__ Wpart)
{
    __shared__ float As[8][64];
    __shared__ float Bs[8][64];
    const int tid = threadIdx.x;
    const int tx  = tid % 16;
    const int ty  = tid / 16;
    const int m0  = blockIdx.y * 64;
    const int n0  = blockIdx.x * 64;
    const int ks  = blockIdx.z * 256;
    float acc[4][4] = {};
    for (int k0 = ks; k0 < ks + 256; k0 += 8) {
        if (tid < 128) {
            const int row = tid >> 1, kq = tid & 1;
            float4 a = *(const float4*)&Wo[(size_t)(m0 + row) * DM + k0 + kq*4];
            As[kq*4+0][row] = a.x; As[kq*4+1][row] = a.y;
            As[kq*4+2][row] = a.z; As[kq*4+3][row] = a.w;
        } else {
            const int i2 = tid - 128;
            const int k  = i2 >> 4;
            const int jq = i2 & 15;
            float4 b = *(const float4*)&Wi[(size_t)(k0 + k) * DI + n0 + jq*4];
            *(float4*)&Bs[k][jq*4] = b;
        }
        __syncthreads();
        #pragma unroll
        for (int k = 0; k < 8; k++) {
            float af[4], bf[4];
            #pragma unroll
            for (int i = 0; i < 4; i++) af[i] = As[k][ty*4 + i];
            #pragma unroll
            for (int j = 0; j < 4; j++) bf[j] = Bs[k][tx*4 + j];
            #pragma unroll
            for (int i = 0; i < 4; i++)
                #pragma unroll
                for (int j = 0; j < 4; j++)
                    acc[i][j] += af[i] * bf[j];
        }
        __syncthreads();
    }
    float* Co = Wpart + (size_t)blockIdx.z * DI * DI;
    #pragma unroll
    for (int i = 0; i < 4; i++)
        #pragma unroll
        for (int j = 0; j < 4; j++)
            Co[(size_t)(m0 + ty*4 + i) * DI + n0 + tx*4 + j] = acc[i][j];
}

// ===== sum split-K partials -> fp16 W; c; y0; + weighted x partials (merged xwp) =====
// grid 1024 x 256: [0,256) W-sum, [256,320) c, [320,832) y0, [832,1024) xwp
__global__ void splitwc_kernel(const float* __restrict__ Wpart,
                               __half* __restrict__ wh,
                               const float* __restrict__ Wo, const float* __restrict__ bi,
                               float* __restrict__ c,
                               const float* __restrict__ mem, float* __restrict__ y0,
                               const float* __restrict__ x, float* __restrict__ part)
{
    const int blk = blockIdx.x;
    const int tid = threadIdx.x;
    if (blk < 256) {
        const int i = blk * 256 + tid;
        float4 s = ((const float4*)Wpart)[i];
        #pragma unroll
        for (int p = 1; p < 4; p++) {
            float4 t = ((const float4*)(Wpart + (size_t)p * DI * DI))[i];
            s.x += t.x; s.y += t.y; s.z += t.z; s.w += t.w;
        }
        __half2 h0 = __floats2half2_rn(s.x, s.y);
        __half2 h1 = __floats2half2_rn(s.z, s.w);
        uint2 H = make_uint2(*(uint32_t*)&h0, *(uint32_t*)&h1);
        *(uint2*)(wh + (size_t)i * 4) = H;
    } else if (blk < 320) {
        const int w = (blk - 256) * 8 + (tid >> 5);
        const int lane = tid & 31;
        float s = 0.f;
        for (int m = lane; m < DM; m += 32) s += Wo[(size_t)w * DM + m] * bi[m];
        #pragma unroll
        for (int o = 16; o; o >>= 1) s += __shfl_down_sync(0xffffffffu, s, o);
        if (!lane) c[w] = s;
    } else if (blk < 832) {
        const int w = (blk - 320) * 8 + (tid >> 5);
        const int lane = tid & 31;
        const int b = w / DI, i = w % DI;
        float s = 0.f;
        for (int m = lane; m < DM; m += 32) s += mem[(size_t)b * DM + m] * Wo[(size_t)i * DM + m];
        #pragma unroll
        for (int o = 16; o; o >>= 1) s += __shfl_down_sync(0xffffffffu, s, o);
        if (!lane) y0[w] = s;
    } else {
        // xwp: weighted x partials, last 3 chunks, 4-way t-split, j in 2 halves
        const int ext  = blk - 832;        // 0..191
        const int cc_s = ext >> 4;         // 0..11
        const int rest = ext & 15;
        const int b    = rest >> 1;
        const int hj   = rest & 1;
        const int j    = hj * 256 + tid;
        const int cc   = cc_s >> 2;        // 0..2
        const int s    = cc_s & 3;         // 0..3
        const int ch   = 13 + cc;
        float w = 0.1f;
        float acc = 0.f;
        const float* xp = x + ((size_t)(b * SS) + ch * 128 + s * 32 + 31) * DI + j;
        #pragma unroll 4
        for (int t = 0; t < 32; t++) {
            acc += w * (*xp);
            w *= 0.9f;
            xp -= DI;
        }
        part[((size_t)(cc * 4 + s) * BB + b) * DI + j] = acc;
    }
}

// ===================================================================
extern "C" void kernel_launch(void* const* d_in, const int* in_sizes, int n_in,
                              void* d_out, int out_size)
{
    const float* x      = (const float*)d_in[0];
    const float* memory = (const float*)d_in[1];
    const float* Wi     = (const float*)d_in[2];
    const float* bi     = (const float*)d_in[3];
    const float* Wo     = (const float*)d_in[4];
    const float* bo     = (const float*)d_in[5];
    float* out = (float*)d_out;

    float *pWpart, *pc, *py0, *plf, *pcar, *pxwp, *pxw;
    __half *pwh;
    cudaGetSymbolAddress((void**)&pWpart, g_Wpart);
    cudaGetSymbolAddress((void**)&pc,     g_c);
    cudaGetSymbolAddress((void**)&py0,    g_y0);
    cudaGetSymbolAddress((void**)&plf,    g_lf);
    cudaGetSymbolAddress((void**)&pcar,   g_carry);
    cudaGetSymbolAddress((void**)&pxwp,   g_xwp);
    cudaGetSymbolAddress((void**)&pxw,    g_xw);
    cudaGetSymbolAddress((void**)&pwh,    g_wh);

    cudaFuncSetAttribute(mma_gemm_kernel, cudaFuncAttributeMaxDynamicSharedMemorySize, GEMM_SMEM);

    // idx 0: W = Wo @ Wi split-K partials (Wi transposed on load)
    wgemm_kernel<<<dim3(8, 8, 4), 256>>>(Wo, Wi, pWpart);
    // idx 1: sum partials -> fp16 W; c; y0; xwp
    splitwc_kernel<<<1024, 256>>>(pWpart, pwh, Wo, bi, pc, memory, py0, x, pxwp);
    // idx 2: fused GEMM + zero-init scan -> out, lf
    mma_gemm_kernel<<<dim3(DI/128, RR/128), 256, GEMM_SMEM>>>(x, pwh, pc, bo, out, plf);
    // idx 3: carry sweep + xw combine
    carry_kernel<<<16, DI>>>(plf, py0, pcar, pxwp, pxw);
    // idx 4: fixup + final memory
    fixfm_kernel<<<640, DI>>>(pcar, out, pxw, Wi, bi, out + (size_t)RR * DI);
}

// round 14
// speedup vs baseline: 1.1248x; 1.1248x over previous
#include <cuda_runtime.h>
#include <cuda_bf16.h>
#include <cuda_fp16.h>
#include <cstdint>
#include <cstddef>

// Problem constants
#define DI  512      // D_IN
#define DM  1024     // D_MEM
#define BB  8        // batch
#define SS  2048     // seq len
#define RR  (BB*SS)  // 16384 rows
#define NCH2 16      // chunks per batch (chunk = 128 steps)

// -------- scratch (static device globals; no allocation) --------
__device__ float g_Wpart[4*DI*DI];                 // split-K partials of W
__device__ float g_c[DI];                          // c = Wo @ bi
__device__ float g_y0[BB*DI];                      // memory @ Wo^T
__device__ float g_lf[BB*NCH2*DI];                 // per-chunk zero-init scan finals
__device__ float g_carry[BB*NCH2*DI];
__device__ float g_xwp[3*4*BB*DI];                 // last-3-chunk 4-way weighted x partials
__device__ float g_xw[BB*DI];
__device__ __align__(16) __half g_wh[DI*DI];       // W in fp16 (single matrix)

// =========================== PTX helpers ===========================
__device__ __forceinline__ uint32_t smem_u32_of(const void* p) {
    uint32_t a;
    asm("{ .reg .u64 t; cvta.to.shared.u64 t, %1; cvt.u32.u64 %0, t; }" : "=r"(a) : "l"(p));
    return a;
}
__device__ __forceinline__ void cp_async16(uint32_t dst, const void* src) {
    asm volatile("cp.async.cg.shared.global [%0], [%1], 16;" :: "r"(dst), "l"(src) : "memory");
}
__device__ __forceinline__ void cp_commit() {
    asm volatile("cp.async.commit_group;" ::: "memory");
}
template<int N> __device__ __forceinline__ void cp_wait() {
    asm volatile("cp.async.wait_group %0;" :: "n"(N) : "memory");
}
__device__ __forceinline__ void ldsm4(uint32_t* r, uint32_t addr) {
    asm volatile("ldmatrix.sync.aligned.m8n8.x4.shared.b16 {%0,%1,%2,%3}, [%4];"
                 : "=r"(r[0]), "=r"(r[1]), "=r"(r[2]), "=r"(r[3]) : "r"(addr));
}
__device__ __forceinline__ void mma16816(float* c, const uint32_t* a, const uint32_t* b) {
    asm volatile(
        "mma.sync.aligned.m16n8k16.row.col.f32.f16.f16.f32 "
        "{%0,%1,%2,%3}, {%4,%5,%6,%7}, {%8,%9}, {%0,%1,%2,%3};"
        : "+f"(c[0]), "+f"(c[1]), "+f"(c[2]), "+f"(c[3])
        : "r"(a[0]), "r"(a[1]), "r"(a[2]), "r"(a[3]), "r"(b[0]), "r"(b[1]));
}

// fp32 x8 -> fp16 hi/lo x8
__device__ __forceinline__ void cvt8h(const float4 a, const float4 b, uint4& H, uint4& L) {
    float f[8] = {a.x, a.y, a.z, a.w, b.x, b.y, b.z, b.w};
    uint32_t h[4], l[4];
    #pragma unroll
    for (int q = 0; q < 4; q++) {
        __half2 hh = __floats2half2_rn(f[2*q], f[2*q+1]);
        float r0 = f[2*q]   - __half2float(__low2half(hh));
        float r1 = f[2*q+1] - __half2float(__high2half(hh));
        __half2 ll = __floats2half2_rn(r0, r1);
        h[q] = *(uint32_t*)&hh;
        l[q] = *(uint32_t*)&ll;
    }
    H = make_uint4(h[0], h[1], h[2], h[3]);
    L = make_uint4(l[0], l[1], l[2], l[3]);
}

// ================== fused tensor-core GEMM + zero-init scan (FROZEN R12 body) ==================
#define KCH    32
#define NCHK   (DI/KCH)          // 16
#define ROWB   80                // padded smem row stride (64B data + 16B pad)
#define MATB   (128*ROWB)        // 10240 bytes per matrix tile
#define STG_B  (3*MATB)          // 30720 per stage (AH, AL, BH)
#define OFF_F  67584             // after epilogue S region (128*132*4)
#define OFF_BO 68608             // bo strip: 128 floats
#define OFF_CS 69120             // c strip: 128 floats
#define GEMM_SMEM 69632

__global__ void __launch_bounds__(256, 2)
mma_gemm_kernel(const float* __restrict__ x,
                const __half* __restrict__ wh,
                const float* __restrict__ cbias, const float* __restrict__ bo,
                float* __restrict__ out, float* __restrict__ lf)
{
    extern __shared__ char smem[];
    const uint32_t sbase = smem_u32_of(smem);
    const int tid  = threadIdx.x;
    const int wid  = tid >> 5;
    const int lane = tid & 31;
    const int wm   = wid & 3;
    const int wn   = wid >> 2;
    const int m0   = blockIdx.y * 128;
    const int n0g  = blockIdx.x * 128;
    const int bch  = blockIdx.y;   // b = bch>>4, chunk = bch&15

    float* F_sm  = (float*)(smem + OFF_F);
    float* bo_sm = (float*)(smem + OFF_BO);
    float* cs_sm = (float*)(smem + OFF_CS);
    if (tid < 128) {
        bo_sm[tid] = bo[n0g + tid];
        cs_sm[tid] = cbias[n0g + tid];
    }

    const float* xg = x + (size_t)m0 * DI;
    const __half* bhg = wh + (size_t)n0g * DI;

    const int lr  = lane & 7;
    const int blk = lane >> 3;
    const uint32_t a_off = (uint32_t)((((blk & 1) * 8 + lr) * ROWB) + ((blk >> 1) * 16));
    const uint32_t b_off = (uint32_t)((((blk >> 1) * 8 + lr) * ROWB) + ((blk & 1) * 16));

    float acc[2][8][4];
    #pragma unroll
    for (int i = 0; i < 2; i++)
        #pragma unroll
        for (int j = 0; j < 8; j++)
            #pragma unroll
            for (int q = 0; q < 4; q++) acc[i][j][q] = 0.f;

    float4 xr[4];

    auto ldA = [&](int ch) {
        const int k0 = ch * KCH;
        #pragma unroll
        for (int u = 0; u < 2; u++) {
            const int idx2 = tid * 2 + u;
            const int r = idx2 >> 2, j = idx2 & 3;
            const float4* sp = (const float4*)(xg + (size_t)r * DI + k0 + j * 8);
            xr[u*2+0] = sp[0];
            xr[u*2+1] = sp[1];
        }
    };
    auto stA = [&](int ch) {
        const uint32_t stg = (uint32_t)((ch & 1) * STG_B);
        #pragma unroll
        for (int u = 0; u < 2; u++) {
            const int idx2 = tid * 2 + u;
            const int r = idx2 >> 2, j = idx2 & 3;
            uint4 H, L;
            cvt8h(xr[u*2+0], xr[u*2+1], H, L);
            *(uint4*)(smem + stg + r * ROWB + j * 16)        = H;
            *(uint4*)(smem + stg + MATB + r * ROWB + j * 16) = L;
        }
    };
    auto issueB = [&](int ch) {
        const int k0 = ch * KCH;
        const uint32_t stg = sbase + (uint32_t)((ch & 1) * STG_B) + 2 * MATB;
        #pragma unroll
        for (int t = 0; t < 2; t++) {
            const int i   = (t << 8) + tid;     // 0..511
            const int row = i >> 2, j = i & 3;
            const uint32_t dst = stg + (uint32_t)(row * ROWB + j * 16);
            cp_async16(dst, bhg + (size_t)row * DI + k0 + j * 8);
        }
        cp_commit();
    };

    ldA(0);
    issueB(0);

    for (int ch = 0; ch < NCHK; ch++) {
        if (ch + 1 < NCHK) issueB(ch + 1);
        stA(ch);
        if (ch + 1 < NCHK) ldA(ch + 1);
        if (ch + 1 < NCHK) cp_wait<1>(); else cp_wait<0>();
        __syncthreads();

        const uint32_t stg = sbase + (uint32_t)((ch & 1) * STG_B);
        const uint32_t sAH = stg;
        const uint32_t sAL = stg + MATB;
        const uint32_t sBH = stg + 2 * MATB;

        #pragma unroll
        for (int kk = 0; kk < 2; kk++) {
            const uint32_t kb = (uint32_t)(kk * 32);
            uint32_t ah[2][4], al[2][4];
            #pragma unroll
            for (int mt = 0; mt < 2; mt++) {
                const uint32_t ro = (uint32_t)((wm * 32 + mt * 16) * ROWB) + kb + a_off;
                ldsm4(ah[mt], sAH + ro);
                ldsm4(al[mt], sAL + ro);
            }
            #pragma unroll
            for (int nb = 0; nb < 4; nb++) {
                const uint32_t ro = (uint32_t)((wn * 64 + nb * 16) * ROWB) + kb + b_off;
                uint32_t bh[4];
                ldsm4(bh, sBH + ro);
                #pragma unroll
                for (int mt = 0; mt < 2; mt++) {
                    mma16816(acc[mt][2*nb+0], ah[mt], bh + 0);
                    mma16816(acc[mt][2*nb+1], ah[mt], bh + 2);
                    mma16816(acc[mt][2*nb+0], al[mt], bh + 0);
                    mma16816(acc[mt][2*nb+1], al[mt], bh + 2);
                }
            }
        }
        __syncthreads();
    }

    // ---- epilogue: dump acc to smem, zero-init local scan, +bo, write out; emit lf ----
    float* S = (float*)smem;   // [128][132] fp32
    #pragma unroll
    for (int mt = 0; mt < 2; mt++) {
        const int r0 = wm * 32 + mt * 16 + (lane >> 2);
        #pragma unroll
        for (int nt = 0; nt < 8; nt++) {
            const int c0 = wn * 64 + nt * 8 + ((lane & 3) * 2);
            S[r0 * 132 + c0]       = acc[mt][nt][0];
            S[r0 * 132 + c0 + 1]   = acc[mt][nt][1];
            S[(r0+8) * 132 + c0]     = acc[mt][nt][2];
            S[(r0+8) * 132 + c0 + 1] = acc[mt][nt][3];
        }
    }
    __syncthreads();

    const int col  = tid & 127;
    const int half = tid >> 7;
    const float cv = cs_sm[col];
    {
        const int tb = half * 64;
        float o = 0.f;
        #pragma unroll 4
        for (int t = 0; t < 64; t++) {
            o = o * 0.9f + 0.1f * (S[(tb + t) * 132 + col] + cv);
            S[(tb + t) * 132 + col] = o;
        }
        F_sm[half * 128 + col] = o;
    }
    __syncthreads();

    if (half == 1) {
        const float f0 = F_sm[col];   // half-0 final
        float p = 0.9f, last = 0.f;
        #pragma unroll 4
        for (int t = 0; t < 64; t++) {
            last = S[(64 + t) * 132 + col] + p * f0;
            S[(64 + t) * 132 + col] = last;
            p *= 0.9f;
        }
        lf[(size_t)bch * DI + n0g + col] = last;   // chunk-final (zero-init)
    }
    __syncthreads();

    #pragma unroll
    for (int it = 0; it < 16; it++) {
        const int idx = tid + it * 256;
        const int row = idx >> 5;
        const int q   = idx & 31;
        float4 s = *(float4*)&S[row * 132 + q * 4];
        const int lc = q * 4;
        s.x += bo_sm[lc]; s.y += bo_sm[lc+1]; s.z += bo_sm[lc+2]; s.w += bo_sm[lc+3];
        *(float4*)(out + (size_t)(m0 + row) * DI + n0g + lc) = s;
    }
}

// ===== carry sweep (lf prefetched, MLP 16) =====
__global__ void carry_kernel(const float* __restrict__ lf, const float* __restrict__ y0,
                             float* __restrict__ carry)
{
    const int b = blockIdx.x, i = threadIdx.x;
    float lfv[NCH2];
    #pragma unroll
    for (int ch = 0; ch < NCH2; ch++)
        lfv[ch] = lf[(size_t)(b * NCH2 + ch) * DI + i];
    float c = y0[b * DI + i];
    const float P = 1.3900845237714473e-06f;   // 0.9^128
    #pragma unroll
    for (int ch = 0; ch < NCH2; ch++) {
        carry[(size_t)(b * NCH2 + ch) * DI + i] = c;
        c = c * P + lfv[ch];
    }
}

// ===== fixup: out += 0.9^{t+1} * carry, 4-way split over t (serial depth 32) =====
__global__ void fixup_kernel(const float* __restrict__ carry, float* __restrict__ out)
{
    const int chs = blockIdx.x;           // 0..63 : ch*4 + s
    const int ch  = chs >> 2;
    const int s   = chs & 3;
    const int b   = blockIdx.y, i = threadIdx.x;
    const float cr = carry[(size_t)(b * NCH2 + ch) * DI + i];
    if (cr == 0.f) return;
    // 0.9^(32s): s=0..3
    const float C32[4] = {1.f, 0.03433683820292512f, 0.0011790184577738583f, 4.0484399061482485e-05f};
    float p = C32[s] * 0.9f;
    float* op = out + (size_t)(b * SS + ch * 128 + s * 32) * DI + i;
    #pragma unroll 4
    for (int t = 0; t < 32; t++) {
        op[(size_t)t * DI] += p * cr;
        p *= 0.9f;
    }
}

// ===== weighted x partials, last 3 chunks only =====
__global__ void xwp_kernel(const float* __restrict__ x, float* __restrict__ part)
{
    const int s  = blockIdx.x & 3;
    const int cc = blockIdx.x >> 2;      // 0..2
    const int b  = blockIdx.y;
    const int j  = threadIdx.x;
    const int ch = 13 + cc;
    float w = 0.1f;
    float acc = 0.f;
    const float* xp = x + ((size_t)(b * SS) + ch * 128 + s * 32 + 31) * DI + j;
    #pragma unroll 4
    for (int t = 0; t < 32; t++) {
        acc += w * (*xp);
        w *= 0.9f;
        xp -= DI;
    }
    part[((size_t)(cc * 4 + s) * BB + b) * DI + j] = acc;
}

#define XC1 0.03433683820292512f            // 0.9^32
#define XC2 (XC1*XC1)
#define XC3 (XC2*XC1)

// ===== combine 12 partials -> xw =====
__global__ void xw_combine_kernel(const float* __restrict__ part, float* __restrict__ xw)
{
    const int b = blockIdx.x, j = threadIdx.x;
    const float P = 1.3900845237714473e-06f;   // 0.9^128
    float v[12];
    #pragma unroll
    for (int q = 0; q < 12; q++)
        v[q] = part[((size_t)q * BB + b) * DI + j];
    float xwc[3];
    #pragma unroll
    for (int cc = 0; cc < 3; cc++)
        xwc[cc] = v[cc*4+3] + XC1*v[cc*4+2] + XC2*v[cc*4+1] + XC3*v[cc*4+0];
    xw[b * DI + j] = xwc[2] + P * xwc[1] + (P * P) * xwc[0];
}

// ================== W = Wo @ Wi, split-K=4 partials (Wi read directly) ==========
__global__ void __launch_bounds__(256)
wgemm_kernel(const float* __restrict__ Wo, const float* __restrict__ Wi,
             float* __restrict__ Wpart)
{
    __shared__ float As[8][64];
    __shared__ float Bs[8][64];
    const int tid = threadIdx.x;
    const int tx  = tid % 16;
    const int ty  = tid / 16;
    const int m0  = blockIdx.y * 64;
    const int n0  = blockIdx.x * 64;
    const int ks  = blockIdx.z * 256;
    float acc[4][4] = {};
    for (int k0 = ks; k0 < ks + 256; k0 += 8) {
        if (tid < 128) {
            const int row = tid >> 1, kq = tid & 1;
            float4 a = *(const float4*)&Wo[(size_t)(m0 + row) * DM + k0 + kq*4];
            As[kq*4+0][row] = a.x; As[kq*4+1][row] = a.y;
            As[kq*4+2][row] = a.z; As[kq*4+3][row] = a.w;
        } else {
            const int i2 = tid - 128;
            const int k  = i2 >> 4;
            const int jq = i2 & 15;
            float4 b = *(const float4*)&Wi[(size_t)(k0 + k) * DI + n0 + jq*4];
            *(float4*)&Bs[k][jq*4] = b;
        }
        __syncthreads();
        #pragma unroll
        for (int k = 0; k < 8; k++) {
            float af[4], bf[4];
            #pragma unroll
            for (int i = 0; i < 4; i++) af[i] = As[k][ty*4 + i];
            #pragma unroll
            for (int j = 0; j < 4; j++) bf[j] = Bs[k][tx*4 + j];
            #pragma unroll
            for (int i = 0; i < 4; i++)
                #pragma unroll
                for (int j = 0; j < 4; j++)
                    acc[i][j] += af[i] * bf[j];
        }
        __syncthreads();
    }
    float* Co = Wpart + (size_t)blockIdx.z * DI * DI;
    #pragma unroll
    for (int i = 0; i < 4; i++)
        #pragma unroll
        for (int j = 0; j < 4; j++)
            Co[(size_t)(m0 + ty*4 + i) * DI + n0 + tx*4 + j] = acc[i][j];
}

// ===== sum split-K partials -> fp16 W; c = Wo@bi; y0 = mem@Wo^T =====
__global__ void splitwc_kernel(const float* __restrict__ Wpart,
                               __half* __restrict__ wh,
                               const float* __restrict__ Wo, const float* __restrict__ bi,
                               float* __restrict__ c,
                               const float* __restrict__ mem, float* __restrict__ y0)
{
    const int blk = blockIdx.x;
    const int tid = threadIdx.x;
    if (blk < 256) {
        const int i = blk * 256 + tid;
        float4 s = ((const float4*)Wpart)[i];
        #pragma unroll
        for (int p = 1; p < 4; p++) {
            float4 t = ((const float4*)(Wpart + (size_t)p * DI * DI))[i];
            s.x += t.x; s.y += t.y; s.z += t.z; s.w += t.w;
        }
        __half2 h0 = __floats2half2_rn(s.x, s.y);
        __half2 h1 = __floats2half2_rn(s.z, s.w);
        uint2 H = make_uint2(*(uint32_t*)&h0, *(uint32_t*)&h1);
        *(uint2*)(wh + (size_t)i * 4) = H;
    } else if (blk < 320) {
        const int w = (blk - 256) * 8 + (tid >> 5);
        const int lane = tid & 31;
        float s = 0.f;
        for (int m = lane; m < DM; m += 32) s += Wo[(size_t)w * DM + m] * bi[m];
        #pragma unroll
        for (int o = 16; o; o >>= 1) s += __shfl_down_sync(0xffffffffu, s, o);
        if (!lane) c[w] = s;
    } else {
        const int w = (blk - 320) * 8 + (tid >> 5);
        const int lane = tid & 31;
        const int b = w / DI, i = w % DI;
        float s = 0.f;
        for (int m = lane; m < DM; m += 32) s += mem[(size_t)b * DM + m] * Wo[(size_t)i * DM + m];
        #pragma unroll
        for (int o = 16; o; o >>= 1) s += __shfl_down_sync(0xffffffffu, s, o);
        if (!lane) y0[w] = s;
    }
}

// ================== final memory: fm = xw @ Wi^T + bi ==================
__global__ void fm_kernel(const float* __restrict__ xw, const float* __restrict__ Wi,
                          const float* __restrict__ bi, float* __restrict__ fm)
{
    int w = (blockIdx.x * blockDim.x + threadIdx.x) >> 5;
    int lane = threadIdx.x & 31;
    if (w >= BB * DM) return;
    int b = w / DM, m = w % DM;
    float s = 0.f;
    for (int j = lane; j < DI; j += 32) s += xw[b * DI + j] * Wi[(size_t)m * DI + j];
    #pragma unroll
    for (int o = 16; o; o >>= 1) s += __shfl_down_sync(0xffffffffu, s, o);
    if (!lane) fm[w] = s + bi[m];
}

// ===================================================================
extern "C" void kernel_launch(void* const* d_in, const int* in_sizes, int n_in,
                              void* d_out, int out_size)
{
    const float* x      = (const float*)d_in[0];
    const float* memory = (const float*)d_in[1];
    const float* Wi     = (const float*)d_in[2];
    const float* bi     = (const float*)d_in[3];
    const float* Wo     = (const float*)d_in[4];
    const float* bo     = (const float*)d_in[5];
    float* out = (float*)d_out;

    float *pWpart, *pc, *py0, *plf, *pcar, *pxwp, *pxw;
    __half *pwh;
    cudaGetSymbolAddress((void**)&pWpart, g_Wpart);
    cudaGetSymbolAddress((void**)&pc,     g_c);
    cudaGetSymbolAddress((void**)&py0,    g_y0);
    cudaGetSymbolAddress((void**)&plf,    g_lf);
    cudaGetSymbolAddress((void**)&pcar,   g_carry);
    cudaGetSymbolAddress((void**)&pxwp,   g_xwp);
    cudaGetSymbolAddress((void**)&pxw,    g_xw);
    cudaGetSymbolAddress((void**)&pwh,    g_wh);

    cudaFuncSetAttribute(mma_gemm_kernel, cudaFuncAttributeMaxDynamicSharedMemorySize, GEMM_SMEM);

    // idx 0: W = Wo @ Wi split-K partials (Wi transposed on load)
    wgemm_kernel<<<dim3(8, 8, 4), 256>>>(Wo, Wi, pWpart);
    // idx 1: sum partials -> fp16 W; c; y0
    splitwc_kernel<<<832, 256>>>(pWpart, pwh, Wo, bi, pc, memory, py0);
    // idx 2: weighted x partials (last 3 chunks only)
    xwp_kernel<<<dim3(12, BB), DI>>>(x, pxwp);
    // idx 3: fused GEMM + zero-init scan -> out, lf
    mma_gemm_kernel<<<dim3(DI/128, RR/128), 256, GEMM_SMEM>>>(x, pwh, pc, bo, out, plf);
    // idx 4: combine -> xw
    xw_combine_kernel<<<BB, DI>>>(pxwp, pxw);
    // idx 5: carry sweep
    carry_kernel<<<BB, DI>>>(plf, py0, pcar);
    // idx 6: fixup out += 0.9^{t+1} * carry (4-way t-split)
    fixup_kernel<<<dim3(NCH2*4, BB), DI>>>(pcar, out);
    // idx 7: final memory
    fm_kernel<<<(BB*DM*32)/256, 256>>>(pxw, Wi, bi, out + (size_t)RR * DI);
}

// round 15
// speedup vs baseline: 1.1423x; 1.0156x over previous
#include <cuda_runtime.h>
#include <cuda_bf16.h>
#include <cuda_fp16.h>
#include <cstdint>
#include <cstddef>

// Problem constants
#define DI  512      // D_IN
#define DM  1024     // D_MEM
#define BB  8        // batch
#define SS  2048     // seq len
#define RR  (BB*SS)  // 16384 rows
#define NCH2 16      // chunks per batch (chunk = 128 steps)

// -------- scratch (static device globals; no allocation) --------
__device__ float g_Wpart[4*DI*DI];                 // split-K partials of W
__device__ float g_c[DI];                          // c = Wo @ bi
__device__ float g_y0[BB*DI];                      // memory @ Wo^T
__device__ float g_lf[BB*NCH2*DI];                 // per-chunk zero-init scan finals
__device__ float g_carry[BB*NCH2*DI];
__device__ float g_xwp[3*4*BB*DI];                 // last-3-chunk 4-way weighted x partials
__device__ float g_xw[BB*DI];
__device__ __align__(16) __half g_wh[DI*DI];       // W in fp16 (single matrix)

// =========================== PTX helpers ===========================
__device__ __forceinline__ uint32_t smem_u32_of(const void* p) {
    uint32_t a;
    asm("{ .reg .u64 t; cvta.to.shared.u64 t, %1; cvt.u32.u64 %0, t; }" : "=r"(a) : "l"(p));
    return a;
}
__device__ __forceinline__ void cp_async16(uint32_t dst, const void* src) {
    asm volatile("cp.async.cg.shared.global [%0], [%1], 16;" :: "r"(dst), "l"(src) : "memory");
}
__device__ __forceinline__ void cp_commit() {
    asm volatile("cp.async.commit_group;" ::: "memory");
}
template<int N> __device__ __forceinline__ void cp_wait() {
    asm volatile("cp.async.wait_group %0;" :: "n"(N) : "memory");
}
__device__ __forceinline__ void ldsm4(uint32_t* r, uint32_t addr) {
    asm volatile("ldmatrix.sync.aligned.m8n8.x4.shared.b16 {%0,%1,%2,%3}, [%4];"
                 : "=r"(r[0]), "=r"(r[1]), "=r"(r[2]), "=r"(r[3]) : "r"(addr));
}
__device__ __forceinline__ void mma16816(float* c, const uint32_t* a, const uint32_t* b) {
    asm volatile(
        "mma.sync.aligned.m16n8k16.row.col.f32.f16.f16.f32 "
        "{%0,%1,%2,%3}, {%4,%5,%6,%7}, {%8,%9}, {%0,%1,%2,%3};"
        : "+f"(c[0]), "+f"(c[1]), "+f"(c[2]), "+f"(c[3])
        : "r"(a[0]), "r"(a[1]), "r"(a[2]), "r"(a[3]), "r"(b[0]), "r"(b[1]));
}

// fp32 x8 -> fp16 hi/lo x8
__device__ __forceinline__ void cvt8h(const float4 a, const float4 b, uint4& H, uint4& L) {
    float f[8] = {a.x, a.y, a.z, a.w, b.x, b.y, b.z, b.w};
    uint32_t h[4], l[4];
    #pragma unroll
    for (int q = 0; q < 4; q++) {
        __half2 hh = __floats2half2_rn(f[2*q], f[2*q+1]);
        float r0 = f[2*q]   - __half2float(__low2half(hh));
        float r1 = f[2*q+1] - __half2float(__high2half(hh));
        __half2 ll = __floats2half2_rn(r0, r1);
        h[q] = *(uint32_t*)&hh;
        l[q] = *(uint32_t*)&ll;
    }
    H = make_uint4(h[0], h[1], h[2], h[3]);
    L = make_uint4(l[0], l[1], l[2], l[3]);
}

// ================== fused tensor-core GEMM + zero-init scan ==================
// fp16 2-product split: v = (xh + xl) @ wh^T.  Mainloop FROZEN (R12 body).
// Epilogue restructured: scan writes out+bo directly (half-0 during scan,
// half-1 during correction); no final read-back loop.
#define KCH    32
#define NCHK   (DI/KCH)          // 16
#define ROWB   80                // padded smem row stride (64B data + 16B pad)
#define MATB   (128*ROWB)        // 10240 bytes per matrix tile
#define STG_B  (3*MATB)          // 30720 per stage (AH, AL, BH)
#define OFF_F  67584             // after epilogue S region (128*132*4)
#define OFF_BO 68608             // bo strip: 128 floats
#define OFF_CS 69120             // c strip: 128 floats
#define GEMM_SMEM 69632

__global__ void __launch_bounds__(256, 2)
mma_gemm_kernel(const float* __restrict__ x,
                const __half* __restrict__ wh,
                const float* __restrict__ cbias, const float* __restrict__ bo,
                float* __restrict__ out, float* __restrict__ lf)
{
    extern __shared__ char smem[];
    const uint32_t sbase = smem_u32_of(smem);
    const int tid  = threadIdx.x;
    const int wid  = tid >> 5;
    const int lane = tid & 31;
    const int wm   = wid & 3;
    const int wn   = wid >> 2;
    const int m0   = blockIdx.y * 128;
    const int n0g  = blockIdx.x * 128;
    const int bch  = blockIdx.y;   // b = bch>>4, chunk = bch&15

    float* F_sm  = (float*)(smem + OFF_F);
    float* bo_sm = (float*)(smem + OFF_BO);
    float* cs_sm = (float*)(smem + OFF_CS);
    if (tid < 128) {
        bo_sm[tid] = bo[n0g + tid];
        cs_sm[tid] = cbias[n0g + tid];
    }

    const float* xg = x + (size_t)m0 * DI;
    const __half* bhg = wh + (size_t)n0g * DI;

    const int lr  = lane & 7;
    const int blk = lane >> 3;
    const uint32_t a_off = (uint32_t)((((blk & 1) * 8 + lr) * ROWB) + ((blk >> 1) * 16));
    const uint32_t b_off = (uint32_t)((((blk >> 1) * 8 + lr) * ROWB) + ((blk & 1) * 16));

    float acc[2][8][4];
    #pragma unroll
    for (int i = 0; i < 2; i++)
        #pragma unroll
        for (int j = 0; j < 8; j++)
            #pragma unroll
            for (int q = 0; q < 4; q++) acc[i][j][q] = 0.f;

    float4 xr[4];

    auto ldA = [&](int ch) {
        const int k0 = ch * KCH;
        #pragma unroll
        for (int u = 0; u < 2; u++) {
            const int idx2 = tid * 2 + u;
            const int r = idx2 >> 2, j = idx2 & 3;
            const float4* sp = (const float4*)(xg + (size_t)r * DI + k0 + j * 8);
            xr[u*2+0] = sp[0];
            xr[u*2+1] = sp[1];
        }
    };
    auto stA = [&](int ch) {
        const uint32_t stg = (uint32_t)((ch & 1) * STG_B);
        #pragma unroll
        for (int u = 0; u < 2; u++) {
            const int idx2 = tid * 2 + u;
            const int r = idx2 >> 2, j = idx2 & 3;
            uint4 H, L;
            cvt8h(xr[u*2+0], xr[u*2+1], H, L);
            *(uint4*)(smem + stg + r * ROWB + j * 16)        = H;
            *(uint4*)(smem + stg + MATB + r * ROWB + j * 16) = L;
        }
    };
    auto issueB = [&](int ch) {
        const int k0 = ch * KCH;
        const uint32_t stg = sbase + (uint32_t)((ch & 1) * STG_B) + 2 * MATB;
        #pragma unroll
        for (int t = 0; t < 2; t++) {
            const int i   = (t << 8) + tid;     // 0..511
            const int row = i >> 2, j = i & 3;
            const uint32_t dst = stg + (uint32_t)(row * ROWB + j * 16);
            cp_async16(dst, bhg + (size_t)row * DI + k0 + j * 8);
        }
        cp_commit();
    };

    ldA(0);
    issueB(0);

    for (int ch = 0; ch < NCHK; ch++) {
        if (ch + 1 < NCHK) issueB(ch + 1);
        stA(ch);
        if (ch + 1 < NCHK) ldA(ch + 1);
        if (ch + 1 < NCHK) cp_wait<1>(); else cp_wait<0>();
        __syncthreads();

        const uint32_t stg = sbase + (uint32_t)((ch & 1) * STG_B);
        const uint32_t sAH = stg;
        const uint32_t sAL = stg + MATB;
        const uint32_t sBH = stg + 2 * MATB;

        #pragma unroll
        for (int kk = 0; kk < 2; kk++) {
            const uint32_t kb = (uint32_t)(kk * 32);
            uint32_t ah[2][4], al[2][4];
            #pragma unroll
            for (int mt = 0; mt < 2; mt++) {
                const uint32_t ro = (uint32_t)((wm * 32 + mt * 16) * ROWB) + kb + a_off;
                ldsm4(ah[mt], sAH + ro);
                ldsm4(al[mt], sAL + ro);
            }
            #pragma unroll
            for (int nb = 0; nb < 4; nb++) {
                const uint32_t ro = (uint32_t)((wn * 64 + nb * 16) * ROWB) + kb + b_off;
                uint32_t bh[4];
                ldsm4(bh, sBH + ro);
                #pragma unroll
                for (int mt = 0; mt < 2; mt++) {
                    mma16816(acc[mt][2*nb+0], ah[mt], bh + 0);
                    mma16816(acc[mt][2*nb+1], ah[mt], bh + 2);
                    mma16816(acc[mt][2*nb+0], al[mt], bh + 0);
                    mma16816(acc[mt][2*nb+1], al[mt], bh + 2);
                }
            }
        }
        __syncthreads();
    }

    // ---- epilogue: dump acc to smem, scan with direct out writes ----
    float* S = (float*)smem;   // [128][132] fp32
    #pragma unroll
    for (int mt = 0; mt < 2; mt++) {
        const int r0 = wm * 32 + mt * 16 + (lane >> 2);
        #pragma unroll
        for (int nt = 0; nt < 8; nt++) {
            const int c0 = wn * 64 + nt * 8 + ((lane & 3) * 2);
            S[r0 * 132 + c0]       = acc[mt][nt][0];
            S[r0 * 132 + c0 + 1]   = acc[mt][nt][1];
            S[(r0+8) * 132 + c0]     = acc[mt][nt][2];
            S[(r0+8) * 132 + c0 + 1] = acc[mt][nt][3];
        }
    }
    __syncthreads();

    const int col  = tid & 127;
    const int half = tid >> 7;
    const float cv  = cs_sm[col];
    const float bov = bo_sm[col];
    float* ocol = out + (size_t)m0 * DI + n0g + col;

    if (half == 0) {
        // half-0: scan values are final -> write out+bo directly
        float o = 0.f;
        #pragma unroll 4
        for (int t = 0; t < 64; t++) {
            o = o * 0.9f + 0.1f * (S[t * 132 + col] + cv);
            ocol[(size_t)t * DI] = o + bov;
        }
        F_sm[col] = o;
    } else {
        // half-1: zero-init partials kept in S until f0 known
        float o = 0.f;
        #pragma unroll 4
        for (int t = 0; t < 64; t++) {
            o = o * 0.9f + 0.1f * (S[(64 + t) * 132 + col] + cv);
            S[(64 + t) * 132 + col] = o;
        }
    }
    __syncthreads();

    if (half == 1) {
        const float f0 = F_sm[col];   // half-0 final
        float p = 0.9f, last = 0.f;
        #pragma unroll 4
        for (int t = 0; t < 64; t++) {
            last = S[(64 + t) * 132 + col] + p * f0;
            ocol[(size_t)(64 + t) * DI] = last + bov;
            p *= 0.9f;
        }
        lf[(size_t)bch * DI + n0g + col] = last;   // chunk-final (zero-init)
    }
}

// ===== carry sweep (lf prefetched, MLP 16) =====
__global__ void carry_kernel(const float* __restrict__ lf, const float* __restrict__ y0,
                             float* __restrict__ carry)
{
    const int b = blockIdx.x, i = threadIdx.x;
    float lfv[NCH2];
    #pragma unroll
    for (int ch = 0; ch < NCH2; ch++)
        lfv[ch] = lf[(size_t)(b * NCH2 + ch) * DI + i];
    float c = y0[b * DI + i];
    const float P = 1.3900845237714473e-06f;   // 0.9^128
    #pragma unroll
    for (int ch = 0; ch < NCH2; ch++) {
        carry[(size_t)(b * NCH2 + ch) * DI + i] = c;
        c = c * P + lfv[ch];
    }
}

// ===== fixup: out += 0.9^{t+1} * carry, 4-way split over t (serial depth 32) =====
__global__ void fixup_kernel(const float* __restrict__ carry, float* __restrict__ out)
{
    const int chs = blockIdx.x;           // 0..63 : ch*4 + s
    const int ch  = chs >> 2;
    const int s   = chs & 3;
    const int b   = blockIdx.y, i = threadIdx.x;
    const float cr = carry[(size_t)(b * NCH2 + ch) * DI + i];
    if (cr == 0.f) return;
    const float C32[4] = {1.f, 0.03433683820292512f, 0.0011790184577738583f, 4.0484399061482485e-05f};
    float p = C32[s] * 0.9f;
    float* op = out + (size_t)(b * SS + ch * 128 + s * 32) * DI + i;
    #pragma unroll 4
    for (int t = 0; t < 32; t++) {
        op[(size_t)t * DI] += p * cr;
        p *= 0.9f;
    }
}

// ===== weighted x partials, last 3 chunks only =====
__global__ void xwp_kernel(const float* __restrict__ x, float* __restrict__ part)
{
    const int s  = blockIdx.x & 3;
    const int cc = blockIdx.x >> 2;      // 0..2
    const int b  = blockIdx.y;
    const int j  = threadIdx.x;
    const int ch = 13 + cc;
    float w = 0.1f;
    float acc = 0.f;
    const float* xp = x + ((size_t)(b * SS) + ch * 128 + s * 32 + 31) * DI + j;
    #pragma unroll 4
    for (int t = 0; t < 32; t++) {
        acc += w * (*xp);
        w *= 0.9f;
        xp -= DI;
    }
    part[((size_t)(cc * 4 + s) * BB + b) * DI + j] = acc;
}

#define XC1 0.03433683820292512f            // 0.9^32
#define XC2 (XC1*XC1)
#define XC3 (XC2*XC1)

// ===== combine 12 partials -> xw =====
__global__ void xw_combine_kernel(const float* __restrict__ part, float* __restrict__ xw)
{
    const int b = blockIdx.x, j = threadIdx.x;
    const float P = 1.3900845237714473e-06f;   // 0.9^128
    float v[12];
    #pragma unroll
    for (int q = 0; q < 12; q++)
        v[q] = part[((size_t)q * BB + b) * DI + j];
    float xwc[3];
    #pragma unroll
    for (int cc = 0; cc < 3; cc++)
        xwc[cc] = v[cc*4+3] + XC1*v[cc*4+2] + XC2*v[cc*4+1] + XC3*v[cc*4+0];
    xw[b * DI + j] = xwc[2] + P * xwc[1] + (P * P) * xwc[0];
}

// ================== W = Wo @ Wi, split-K=4 partials (Wi read directly) ==========
__global__ void __launch_bounds__(256)
wgemm_kernel(const float* __restrict__ Wo, const float* __restrict__ Wi,
             float* __restrict__ Wpart)
{
    __shared__ float As[8][64];
    __shared__ float Bs[8][64];
    const int tid = threadIdx.x;
    const int tx  = tid % 16;
    const int ty  = tid / 16;
    const int m0  = blockIdx.y * 64;
    const int n0  = blockIdx.x * 64;
    const int ks  = blockIdx.z * 256;
    float acc[4][4] = {};
    for (int k0 = ks; k0 < ks + 256; k0 += 8) {
        if (tid < 128) {
            const int row = tid >> 1, kq = tid & 1;
            float4 a = *(const float4*)&Wo[(size_t)(m0 + row) * DM + k0 + kq*4];
            As[kq*4+0][row] = a.x; As[kq*4+1][row] = a.y;
            As[kq*4+2][row] = a.z; As[kq*4+3][row] = a.w;
        } else {
            const int i2 = tid - 128;
            const int k  = i2 >> 4;
            const int jq = i2 & 15;
            float4 b = *(const float4*)&Wi[(size_t)(k0 + k) * DI + n0 + jq*4];
            *(float4*)&Bs[k][jq*4] = b;
        }
        __syncthreads();
        #pragma unroll
        for (int k = 0; k < 8; k++) {
            float af[4], bf[4];
            #pragma unroll
            for (int i = 0; i < 4; i++) af[i] = As[k][ty*4 + i];
            #pragma unroll
            for (int j = 0; j < 4; j++) bf[j] = Bs[k][tx*4 + j];
            #pragma unroll
            for (int i = 0; i < 4; i++)
                #pragma unroll
                for (int j = 0; j < 4; j++)
                    acc[i][j] += af[i] * bf[j];
        }
        __syncthreads();
    }
    float* Co = Wpart + (size_t)blockIdx.z * DI * DI;
    #pragma unroll
    for (int i = 0; i < 4; i++)
        #pragma unroll
        for (int j = 0; j < 4; j++)
            Co[(size_t)(m0 + ty*4 + i) * DI + n0 + tx*4 + j] = acc[i][j];
}

// ===== sum split-K partials -> fp16 W; c = Wo@bi; y0 = mem@Wo^T =====
__global__ void splitwc_kernel(const float* __restrict__ Wpart,
                               __half* __restrict__ wh,
                               const float* __restrict__ Wo, const float* __restrict__ bi,
                               float* __restrict__ c,
                               const float* __restrict__ mem, float* __restrict__ y0)
{
    const int blk = blockIdx.x;
    const int tid = threadIdx.x;
    if (blk < 256) {
        const int i = blk * 256 + tid;
        float4 s = ((const float4*)Wpart)[i];
        #pragma unroll
        for (int p = 1; p < 4; p++) {
            float4 t = ((const float4*)(Wpart + (size_t)p * DI * DI))[i];
            s.x += t.x; s.y += t.y; s.z += t.z; s.w += t.w;
        }
        __half2 h0 = __floats2half2_rn(s.x, s.y);
        __half2 h1 = __floats2half2_rn(s.z, s.w);
        uint2 H = make_uint2(*(uint32_t*)&h0, *(uint32_t*)&h1);
        *(uint2*)(wh + (size_t)i * 4) = H;
    } else if (blk < 320) {
        const int w = (blk - 256) * 8 + (tid >> 5);
        const int lane = tid & 31;
        float s = 0.f;
        for (int m = lane; m < DM; m += 32) s += Wo[(size_t)w * DM + m] * bi[m];
        #pragma unroll
        for (int o = 16; o; o >>= 1) s += __shfl_down_sync(0xffffffffu, s, o);
        if (!lane) c[w] = s;
    } else {
        const int w = (blk - 320) * 8 + (tid >> 5);
        const int lane = tid & 31;
        const int b = w / DI, i = w % DI;
        float s = 0.f;
        for (int m = lane; m < DM; m += 32) s += mem[(size_t)b * DM + m] * Wo[(size_t)i * DM + m];
        #pragma unroll
        for (int o = 16; o; o >>= 1) s += __shfl_down_sync(0xffffffffu, s, o);
        if (!lane) y0[w] = s;
    }
}

// ================== final memory: fm = xw @ Wi^T + bi ==================
__global__ void fm_kernel(const float* __restrict__ xw, const float* __restrict__ Wi,
                          const float* __restrict__ bi, float* __restrict__ fm)
{
    int w = (blockIdx.x * blockDim.x + threadIdx.x) >> 5;
    int lane = threadIdx.x & 31;
    if (w >= BB * DM) return;
    int b = w / DM, m = w % DM;
    float s = 0.f;
    for (int j = lane; j < DI; j += 32) s += xw[b * DI + j] * Wi[(size_t)m * DI + j];
    #pragma unroll
    for (int o = 16; o; o >>= 1) s += __shfl_down_sync(0xffffffffu, s, o);
    if (!lane) fm[w] = s + bi[m];
}

// ===================================================================
extern "C" void kernel_launch(void* const* d_in, const int* in_sizes, int n_in,
                              void* d_out, int out_size)
{
    const float* x      = (const float*)d_in[0];
    const float* memory = (const float*)d_in[1];
    const float* Wi     = (const float*)d_in[2];
    const float* bi     = (const float*)d_in[3];
    const float* Wo     = (const float*)d_in[4];
    const float* bo     = (const float*)d_in[5];
    float* out = (float*)d_out;

    float *pWpart, *pc, *py0, *plf, *pcar, *pxwp, *pxw;
    __half *pwh;
    cudaGetSymbolAddress((void**)&pWpart, g_Wpart);
    cudaGetSymbolAddress((void**)&pc,     g_c);
    cudaGetSymbolAddress((void**)&py0,    g_y0);
    cudaGetSymbolAddress((void**)&plf,    g_lf);
    cudaGetSymbolAddress((void**)&pcar,   g_carry);
    cudaGetSymbolAddress((void**)&pxwp,   g_xwp);
    cudaGetSymbolAddress((void**)&pxw,    g_xw);
    cudaGetSymbolAddress((void**)&pwh,    g_wh);

    cudaFuncSetAttribute(mma_gemm_kernel, cudaFuncAttributeMaxDynamicSharedMemorySize, GEMM_SMEM);

    // idx 0: W = Wo @ Wi split-K partials (Wi transposed on load)
    wgemm_kernel<<<dim3(8, 8, 4), 256>>>(Wo, Wi, pWpart);
    // idx 1: sum partials -> fp16 W; c; y0
    splitwc_kernel<<<832, 256>>>(pWpart, pwh, Wo, bi, pc, memory, py0);
    // idx 2: weighted x partials (last 3 chunks only)
    xwp_kernel<<<dim3(12, BB), DI>>>(x, pxwp);
    // idx 3: fused GEMM + zero-init scan -> out, lf
    mma_gemm_kernel<<<dim3(DI/128, RR/128), 256, GEMM_SMEM>>>(x, pwh, pc, bo, out, plf);
    // idx 4: combine -> xw
    xw_combine_kernel<<<BB, DI>>>(pxwp, pxw);
    // idx 5: carry sweep
    carry_kernel<<<BB, DI>>>(plf, py0, pcar);
    // idx 6: fixup out += 0.9^{t+1} * carry (4-way t-split)
    fixup_kernel<<<dim3(NCH2*4, BB), DI>>>(pcar, out);
    // idx 7: final memory
    fm_kernel<<<(BB*DM*32)/256, 256>>>(pxw, Wi, bi, out + (size_t)RR * DI);
}

// round 17
// speedup vs baseline: 1.3794x; 1.2075x over previous
#include <cuda_runtime.h>
#include <cuda_bf16.h>
#include <cuda_fp16.h>
#include <cstdint>
#include <cstddef>

// Problem constants
#define DI  512      // D_IN
#define DM  1024     // D_MEM
#define BB  8        // batch
#define SS  2048     // seq len
#define RR  (BB*SS)  // 16384 rows
#define NCH2 16      // chunks per batch (chunk = 128 steps)

// -------- scratch (static device globals; no allocation) --------
__device__ float g_Wpart[4*DI*DI];                 // split-K partials of W
__device__ float g_c[DI];                          // c = Wo @ bi
__device__ float g_y0[BB*DI];                      // memory @ Wo^T
__device__ float g_lf[BB*NCH2*DI];                 // per-chunk zero-init scan finals
__device__ float g_carry[BB*NCH2*DI];
__device__ float g_xwp[3*4*BB*DI];                 // last-3-chunk 4-way weighted x partials
__device__ float g_xw[BB*DI];
__device__ __align__(16) __half g_wh[DI*DI];       // W in fp16 (single matrix)

// =========================== PTX helpers ===========================
__device__ __forceinline__ uint32_t smem_u32_of(const void* p) {
    uint32_t a;
    asm("{ .reg .u64 t; cvta.to.shared.u64 t, %1; cvt.u32.u64 %0, t; }" : "=r"(a) : "l"(p));
    return a;
}
__device__ __forceinline__ void cp_async16(uint32_t dst, const void* src) {
    asm volatile("cp.async.cg.shared.global [%0], [%1], 16;" :: "r"(dst), "l"(src) : "memory");
}
__device__ __forceinline__ void cp_commit() {
    asm volatile("cp.async.commit_group;" ::: "memory");
}
template<int N> __device__ __forceinline__ void cp_wait() {
    asm volatile("cp.async.wait_group %0;" :: "n"(N) : "memory");
}
__device__ __forceinline__ void ldsm4(uint32_t* r, uint32_t addr) {
    asm volatile("ldmatrix.sync.aligned.m8n8.x4.shared.b16 {%0,%1,%2,%3}, [%4];"
                 : "=r"(r[0]), "=r"(r[1]), "=r"(r[2]), "=r"(r[3]) : "r"(addr));
}
__device__ __forceinline__ void mma16816(float* c, const uint32_t* a, const uint32_t* b) {
    asm volatile(
        "mma.sync.aligned.m16n8k16.row.col.f32.f16.f16.f32 "
        "{%0,%1,%2,%3}, {%4,%5,%6,%7}, {%8,%9}, {%0,%1,%2,%3};"
        : "+f"(c[0]), "+f"(c[1]), "+f"(c[2]), "+f"(c[3])
        : "r"(a[0]), "r"(a[1]), "r"(a[2]), "r"(a[3]), "r"(b[0]), "r"(b[1]));
}

// fp32 x8 -> fp16 x8 (single rounding; no lo residual)
__device__ __forceinline__ void cvt8s(const float4 a, const float4 b, uint4& H) {
    float f[8] = {a.x, a.y, a.z, a.w, b.x, b.y, b.z, b.w};
    uint32_t h[4];
    #pragma unroll
    for (int q = 0; q < 4; q++) {
        __half2 hh = __floats2half2_rn(f[2*q], f[2*q+1]);
        h[q] = *(uint32_t*)&hh;
    }
    H = make_uint4(h[0], h[1], h[2], h[3]);
}

// ================== fused tensor-core GEMM + zero-init scan ==================
// Plain fp16 GEMM: v = xh @ wh^T (single product; ~3e-4 rel, under the 1e-3
// gate). CTA tile 128x128, BK=32, double-buffered. Epilogue: scan writes
// out+bo directly; emit lf.
#define KCH    32
#define NCHK   (DI/KCH)          // 16
#define ROWB   80                // padded smem row stride (64B data + 16B pad)
#define MATB   (128*ROWB)        // 10240 bytes per matrix tile
#define STG_B  (2*MATB)          // 20480 per stage (AH, BH)
#define OFF_F  67584             // after epilogue S region (128*132*4)
#define OFF_BO 68608             // bo strip: 128 floats
#define OFF_CS 69120             // c strip: 128 floats
#define GEMM_SMEM 69632

__global__ void __launch_bounds__(256, 2)
mma_gemm_kernel(const float* __restrict__ x,
                const __half* __restrict__ wh,
                const float* __restrict__ cbias, const float* __restrict__ bo,
                float* __restrict__ out, float* __restrict__ lf)
{
    extern __shared__ char smem[];
    const uint32_t sbase = smem_u32_of(smem);
    const int tid  = threadIdx.x;
    const int wid  = tid >> 5;
    const int lane = tid & 31;
    const int wm   = wid & 3;
    const int wn   = wid >> 2;
    const int m0   = blockIdx.y * 128;
    const int n0g  = blockIdx.x * 128;
    const int bch  = blockIdx.y;   // b = bch>>4, chunk = bch&15

    float* F_sm  = (float*)(smem + OFF_F);
    float* bo_sm = (float*)(smem + OFF_BO);
    float* cs_sm = (float*)(smem + OFF_CS);
    if (tid < 128) {
        bo_sm[tid] = bo[n0g + tid];
        cs_sm[tid] = cbias[n0g + tid];
    }

    const float* xg = x + (size_t)m0 * DI;
    const __half* bhg = wh + (size_t)n0g * DI;

    const int lr  = lane & 7;
    const int blk = lane >> 3;
    const uint32_t a_off = (uint32_t)((((blk & 1) * 8 + lr) * ROWB) + ((blk >> 1) * 16));
    const uint32_t b_off = (uint32_t)((((blk >> 1) * 8 + lr) * ROWB) + ((blk & 1) * 16));

    float acc[2][8][4];
    #pragma unroll
    for (int i = 0; i < 2; i++)
        #pragma unroll
        for (int j = 0; j < 8; j++)
            #pragma unroll
            for (int q = 0; q < 4; q++) acc[i][j][q] = 0.f;

    float4 xr[4];

    auto ldA = [&](int ch) {
        const int k0 = ch * KCH;
        #pragma unroll
        for (int u = 0; u < 2; u++) {
            const int idx2 = tid * 2 + u;
            const int r = idx2 >> 2, j = idx2 & 3;
            const float4* sp = (const float4*)(xg + (size_t)r * DI + k0 + j * 8);
            xr[u*2+0] = sp[0];
            xr[u*2+1] = sp[1];
        }
    };
    auto stA = [&](int ch) {
        const uint32_t stg = (uint32_t)((ch & 1) * STG_B);
        #pragma unroll
        for (int u = 0; u < 2; u++) {
            const int idx2 = tid * 2 + u;
            const int r = idx2 >> 2, j = idx2 & 3;
            uint4 H;
            cvt8s(xr[u*2+0], xr[u*2+1], H);
            *(uint4*)(smem + stg + r * ROWB + j * 16) = H;
        }
    };
    auto issueB = [&](int ch) {
        const int k0 = ch * KCH;
        const uint32_t stg = sbase + (uint32_t)((ch & 1) * STG_B) + MATB;
        #pragma unroll
        for (int t = 0; t < 2; t++) {
            const int i   = (t << 8) + tid;     // 0..511
            const int row = i >> 2, j = i & 3;
            const uint32_t dst = stg + (uint32_t)(row * ROWB + j * 16);
            cp_async16(dst, bhg + (size_t)row * DI + k0 + j * 8);
        }
        cp_commit();
    };

    ldA(0);
    issueB(0);

    for (int ch = 0; ch < NCHK; ch++) {
        if (ch + 1 < NCHK) issueB(ch + 1);
        stA(ch);
        if (ch + 1 < NCHK) ldA(ch + 1);
        if (ch + 1 < NCHK) cp_wait<1>(); else cp_wait<0>();
        __syncthreads();

        const uint32_t stg = sbase + (uint32_t)((ch & 1) * STG_B);
        const uint32_t sAH = stg;
        const uint32_t sBH = stg + MATB;

        #pragma unroll
        for (int kk = 0; kk < 2; kk++) {
            const uint32_t kb = (uint32_t)(kk * 32);
            uint32_t ah[2][4];
            #pragma unroll
            for (int mt = 0; mt < 2; mt++) {
                const uint32_t ro = (uint32_t)((wm * 32 + mt * 16) * ROWB) + kb + a_off;
                ldsm4(ah[mt], sAH + ro);
            }
            #pragma unroll
            for (int nb = 0; nb < 4; nb++) {
                const uint32_t ro = (uint32_t)((wn * 64 + nb * 16) * ROWB) + kb + b_off;
                uint32_t bh[4];
                ldsm4(bh, sBH + ro);
                #pragma unroll
                for (int mt = 0; mt < 2; mt++) {
                    mma16816(acc[mt][2*nb+0], ah[mt], bh + 0);
                    mma16816(acc[mt][2*nb+1], ah[mt], bh + 2);
                }
            }
        }
        __syncthreads();
    }

    // ---- epilogue: dump acc to smem, scan with direct out writes ----
    float* S = (float*)smem;   // [128][132] fp32
    #pragma unroll
    for (int mt = 0; mt < 2; mt++) {
        const int r0 = wm * 32 + mt * 16 + (lane >> 2);
        #pragma unroll
        for (int nt = 0; nt < 8; nt++) {
            const int c0 = wn * 64 + nt * 8 + ((lane & 3) * 2);
            S[r0 * 132 + c0]       = acc[mt][nt][0];
            S[r0 * 132 + c0 + 1]   = acc[mt][nt][1];
            S[(r0+8) * 132 + c0]     = acc[mt][nt][2];
            S[(r0+8) * 132 + c0 + 1] = acc[mt][nt][3];
        }
    }
    __syncthreads();

    const int col  = tid & 127;
    const int half = tid >> 7;
    const float cv  = cs_sm[col];
    const float bov = bo_sm[col];
    float* ocol = out + (size_t)m0 * DI + n0g + col;

    if (half == 0) {
        // half-0: scan values are final -> write out+bo directly
        float o = 0.f;
        #pragma unroll 4
        for (int t = 0; t < 64; t++) {
            o = o * 0.9f + 0.1f * (S[t * 132 + col] + cv);
            ocol[(size_t)t * DI] = o + bov;
        }
        F_sm[col] = o;
    } else {
        // half-1: zero-init partials kept in S until f0 known
        float o = 0.f;
        #pragma unroll 4
        for (int t = 0; t < 64; t++) {
            o = o * 0.9f + 0.1f * (S[(64 + t) * 132 + col] + cv);
            S[(64 + t) * 132 + col] = o;
        }
    }
    __syncthreads();

    if (half == 1) {
        const float f0 = F_sm[col];   // half-0 final
        float p = 0.9f, last = 0.f;
        #pragma unroll 4
        for (int t = 0; t < 64; t++) {
            last = S[(64 + t) * 132 + col] + p * f0;
            ocol[(size_t)(64 + t) * DI] = last + bov;
            p *= 0.9f;
        }
        lf[(size_t)bch * DI + n0g + col] = last;   // chunk-final (zero-init)
    }
}

// ===== carry sweep (lf prefetched, MLP 16) =====
__global__ void carry_kernel(const float* __restrict__ lf, const float* __restrict__ y0,
                             float* __restrict__ carry)
{
    const int b = blockIdx.x, i = threadIdx.x;
    float lfv[NCH2];
    #pragma unroll
    for (int ch = 0; ch < NCH2; ch++)
        lfv[ch] = lf[(size_t)(b * NCH2 + ch) * DI + i];
    float c = y0[b * DI + i];
    const float P = 1.3900845237714473e-06f;   // 0.9^128
    #pragma unroll
    for (int ch = 0; ch < NCH2; ch++) {
        carry[(size_t)(b * NCH2 + ch) * DI + i] = c;
        c = c * P + lfv[ch];
    }
}

// ===== fixup: out += 0.9^{t+1} * carry, 4-way split over t (serial depth 32) =====
__global__ void fixup_kernel(const float* __restrict__ carry, float* __restrict__ out)
{
    const int chs = blockIdx.x;           // 0..63 : ch*4 + s
    const int ch  = chs >> 2;
    const int s   = chs & 3;
    const int b   = blockIdx.y, i = threadIdx.x;
    const float cr = carry[(size_t)(b * NCH2 + ch) * DI + i];
    if (cr == 0.f) return;
    const float C32[4] = {1.f, 0.03433683820292512f, 0.0011790184577738583f, 4.0484399061482485e-05f};
    float p = C32[s] * 0.9f;
    float* op = out + (size_t)(b * SS + ch * 128 + s * 32) * DI + i;
    #pragma unroll 4
    for (int t = 0; t < 32; t++) {
        op[(size_t)t * DI] += p * cr;
        p *= 0.9f;
    }
}

// ===== weighted x partials, last 3 chunks only =====
__global__ void xwp_kernel(const float* __restrict__ x, float* __restrict__ part)
{
    const int s  = blockIdx.x & 3;
    const int cc = blockIdx.x >> 2;      // 0..2
    const int b  = blockIdx.y;
    const int j  = threadIdx.x;
    const int ch = 13 + cc;
    float w = 0.1f;
    float acc = 0.f;
    const float* xp = x + ((size_t)(b * SS) + ch * 128 + s * 32 + 31) * DI + j;
    #pragma unroll 4
    for (int t = 0; t < 32; t++) {
        acc += w * (*xp);
        w *= 0.9f;
        xp -= DI;
    }
    part[((size_t)(cc * 4 + s) * BB + b) * DI + j] = acc;
}

#define XC1 0.03433683820292512f            // 0.9^32
#define XC2 (XC1*XC1)
#define XC3 (XC2*XC1)

// ===== combine 12 partials -> xw =====
__global__ void xw_combine_kernel(const float* __restrict__ part, float* __restrict__ xw)
{
    const int b = blockIdx.x, j = threadIdx.x;
    const float P = 1.3900845237714473e-06f;   // 0.9^128
    float v[12];
    #pragma unroll
    for (int q = 0; q < 12; q++)
        v[q] = part[((size_t)q * BB + b) * DI + j];
    float xwc[3];
    #pragma unroll
    for (int cc = 0; cc < 3; cc++)
        xwc[cc] = v[cc*4+3] + XC1*v[cc*4+2] + XC2*v[cc*4+1] + XC3*v[cc*4+0];
    xw[b * DI + j] = xwc[2] + P * xwc[1] + (P * P) * xwc[0];
}

// ================== W = Wo @ Wi, split-K=4 partials (Wi read directly) ==========
__global__ void __launch_bounds__(256)
wgemm_kernel(const float* __restrict__ Wo, const float* __restrict__ Wi,
             float* __restrict__ Wpart)
{
    __shared__ float As[8][64];
    __shared__ float Bs[8][64];
    const int tid = threadIdx.x;
    const int tx  = tid % 16;
    const int ty  = tid / 16;
    const int m0  = blockIdx.y * 64;
    const int n0  = blockIdx.x * 64;
    const int ks  = blockIdx.z * 256;
    float acc[4][4] = {};
    for (int k0 = ks; k0 < ks + 256; k0 += 8) {
        if (tid < 128) {
            const int row = tid >> 1, kq = tid & 1;
            float4 a = *(const float4*)&Wo[(size_t)(m0 + row) * DM + k0 + kq*4];
            As[kq*4+0][row] = a.x; As[kq*4+1][row] = a.y;
            As[kq*4+2][row] = a.z; As[kq*4+3][row] = a.w;
        } else {
            const int i2 = tid - 128;
            const int k  = i2 >> 4;
            const int jq = i2 & 15;
            float4 b = *(const float4*)&Wi[(size_t)(k0 + k) * DI + n0 + jq*4];
            *(float4*)&Bs[k][jq*4] = b;
        }
        __syncthreads();
        #pragma unroll
        for (int k = 0; k < 8; k++) {
            float af[4], bf[4];
            #pragma unroll
            for (int i = 0; i < 4; i++) af[i] = As[k][ty*4 + i];
            #pragma unroll
            for (int j = 0; j < 4; j++) bf[j] = Bs[k][tx*4 + j];
            #pragma unroll
            for (int i = 0; i < 4; i++)
                #pragma unroll
                for (int j = 0; j < 4; j++)
                    acc[i][j] += af[i] * bf[j];
        }
        __syncthreads();
    }
    float* Co = Wpart + (size_t)blockIdx.z * DI * DI;
    #pragma unroll
    for (int i = 0; i < 4; i++)
        #pragma unroll
        for (int j = 0; j < 4; j++)
            Co[(size_t)(m0 + ty*4 + i) * DI + n0 + tx*4 + j] = acc[i][j];
}

// ===== sum split-K partials -> fp16 W; c = Wo@bi; y0 = mem@Wo^T =====
__global__ void splitwc_kernel(const float* __restrict__ Wpart,
                               __half* __restrict__ wh,
                               const float* __restrict__ Wo, const float* __restrict__ bi,
                               float* __restrict__ c,
                               const float* __restrict__ mem, float* __restrict__ y0)
{
    const int blk = blockIdx.x;
    const int tid = threadIdx.x;
    if (blk < 256) {
        const int i = blk * 256 + tid;
        float4 s = ((const float4*)Wpart)[i];
        #pragma unroll
        for (int p = 1; p < 4; p++) {
            float4 t = ((const float4*)(Wpart + (size_t)p * DI * DI))[i];
            s.x += t.x; s.y += t.y; s.z += t.z; s.w += t.w;
        }
        __half2 h0 = __floats2half2_rn(s.x, s.y);
        __half2 h1 = __floats2half2_rn(s.z, s.w);
        uint2 H = make_uint2(*(uint32_t*)&h0, *(uint32_t*)&h1);
        *(uint2*)(wh + (size_t)i * 4) = H;
    } else if (blk < 320) {
        const int w = (blk - 256) * 8 + (tid >> 5);
        const int lane = tid & 31;
        float s = 0.f;
        for (int m = lane; m < DM; m += 32) s += Wo[(size_t)w * DM + m] * bi[m];
        #pragma unroll
        for (int o = 16; o; o >>= 1) s += __shfl_down_sync(0xffffffffu, s, o);
        if (!lane) c[w] = s;
    } else {
        const int w = (blk - 320) * 8 + (tid >> 5);
        const int lane = tid & 31;
        const int b = w / DI, i = w % DI;
        float s = 0.f;
        for (int m = lane; m < DM; m += 32) s += mem[(size_t)b * DM + m] * Wo[(size_t)i * DM + m];
        #pragma unroll
        for (int o = 16; o; o >>= 1) s += __shfl_down_sync(0xffffffffu, s, o);
        if (!lane) y0[w] = s;
    }
}

// ================== final memory: fm = xw @ Wi^T + bi ==================
__global__ void fm_kernel(const float* __restrict__ xw, const float* __restrict__ Wi,
                          const float* __restrict__ bi, float* __restrict__ fm)
{
    int w = (blockIdx.x * blockDim.x + threadIdx.x) >> 5;
    int lane = threadIdx.x & 31;
    if (w >= BB * DM) return;
    int b = w / DM, m = w % DM;
    float s = 0.f;
    for (int j = lane; j < DI; j += 32) s += xw[b * DI + j] * Wi[(size_t)m * DI + j];
    #pragma unroll
    for (int o = 16; o; o >>= 1) s += __shfl_down_sync(0xffffffffu, s, o);
    if (!lane) fm[w] = s + bi[m];
}

// ===================================================================
extern "C" void kernel_launch(void* const* d_in, const int* in_sizes, int n_in,
                              void* d_out, int out_size)
{
    const float* x      = (const float*)d_in[0];
    const float* memory = (const float*)d_in[1];
    const float* Wi     = (const float*)d_in[2];
    const float* bi     = (const float*)d_in[3];
    const float* Wo     = (const float*)d_in[4];
    const float* bo     = (const float*)d_in[5];
    float* out = (float*)d_out;

    float *pWpart, *pc, *py0, *plf, *pcar, *pxwp, *pxw;
    __half *pwh;
    cudaGetSymbolAddress((void**)&pWpart, g_Wpart);
    cudaGetSymbolAddress((void**)&pc,     g_c);
    cudaGetSymbolAddress((void**)&py0,    g_y0);
    cudaGetSymbolAddress((void**)&plf,    g_lf);
    cudaGetSymbolAddress((void**)&pcar,   g_carry);
    cudaGetSymbolAddress((void**)&pxwp,   g_xwp);
    cudaGetSymbolAddress((void**)&pxw,    g_xw);
    cudaGetSymbolAddress((void**)&pwh,    g_wh);

    cudaFuncSetAttribute(mma_gemm_kernel, cudaFuncAttributeMaxDynamicSharedMemorySize, GEMM_SMEM);

    // idx 0: W = Wo @ Wi split-K partials (Wi transposed on load)
    wgemm_kernel<<<dim3(8, 8, 4), 256>>>(Wo, Wi, pWpart);
    // idx 1: sum partials -> fp16 W; c; y0
    splitwc_kernel<<<832, 256>>>(pWpart, pwh, Wo, bi, pc, memory, py0);
    // idx 2: weighted x partials (last 3 chunks only)
    xwp_kernel<<<dim3(12, BB), DI>>>(x, pxwp);
    // idx 3: fused GEMM + zero-init scan -> out, lf
    mma_gemm_kernel<<<dim3(DI/128, RR/128), 256, GEMM_SMEM>>>(x, pwh, pc, bo, out, plf);
    // idx 4: combine -> xw
    xw_combine_kernel<<<BB, DI>>>(pxwp, pxw);
    // idx 5: carry sweep
    carry_kernel<<<BB, DI>>>(plf, py0, pcar);
    // idx 6: fixup out += 0.9^{t+1} * carry (4-way t-split)
    fixup_kernel<<<dim3(NCH2*4, BB), DI>>>(pcar, out);
    // idx 7: final memory
    fm_kernel<<<(BB*DM*32)/256, 256>>>(pxw, Wi, bi, out + (size_t)RR * DI);
}